// round 6
// baseline (speedup 1.0000x reference)
#include <cuda_runtime.h>

#define RR 3
#define NN 50000
#define EE 1000000
#define BB 2048
#define INP 256
#define HID 512
#define OUTD 256

// ---------------- static scratch (no allocations allowed) ----------------
__device__ int   g_is64;             // 1 if index inputs are int64, 0 if int32
__device__ int   g_bn[BB];           // batch_nodes as int32
__device__ unsigned char g_inb[NN];
__device__ unsigned char g_app[RR][NN];
__device__ int   g_newid[RR][NN];
__device__ int   g_cnt[RR];
__device__ int   g_ks[RR][EE];
__device__ int   g_kd[RR][EE];
__device__ float g_deg[RR][BB];
__device__ float g_dinv[RR][BB];
__device__ float g_xw1[(size_t)RR * BB * HID];
__device__ float g_h  [(size_t)RR * BB * HID];
__device__ float g_xw2[(size_t)RR * BB * OUTD];
__device__ float g_bnsum[RR][HID];
__device__ float g_bnsq [RR][HID];
__device__ float g_bna  [RR][HID];   // gamma * istd
__device__ float g_bnb  [RR][HID];   // beta - mean * gamma * istd

__device__ __forceinline__ int ld_idx(const void* p, size_t i, int is64) {
    return is64 ? (int)((const long long*)p)[i] : ((const int*)p)[i];
}

// ---------------- dtype probe + index conversion ----------------
__global__ void k_detect(const void* bn) {
    // batch_nodes: sorted, distinct, 0 <= v < NN. If backing store is int32,
    // the int64 view of element 0 is bn32[0] | (bn32[1]<<32) >= 2^32.
    long long v = ((const long long*)bn)[0];
    g_is64 = (v >= 0 && v < NN) ? 1 : 0;
}

__global__ void k_cvt(const void* bn) {
    int i = blockIdx.x * blockDim.x + threadIdx.x;
    if (i < BB) g_bn[i] = ld_idx(bn, i, g_is64);
}

// ---------------- init / bookkeeping ----------------
__global__ void k_init() {
    int i = blockIdx.x * blockDim.x + threadIdx.x;
    if (i < (RR * NN) / 4) ((int*)g_app)[i] = 0;          // 37500
    if (i < NN / 4)        ((int*)g_inb)[i] = 0;          // 12500
    if (i < RR)            g_cnt[i] = 0;
    if (i < RR * HID) { ((float*)g_bnsum)[i] = 0.f; ((float*)g_bnsq)[i] = 0.f; }
    if (i < RR * BB)       ((float*)g_deg)[i] = 1.0f;     // self-loop
}

__global__ void k_setb() {
    int i = blockIdx.x * blockDim.x + threadIdx.x;
    if (i < BB) g_inb[g_bn[i]] = 1;
}

// mask edges, mark appearing nodes, compact kept edges (original node ids)
__global__ void k_mask(const void* __restrict__ ei) {
    int r = blockIdx.y;
    int e = blockIdx.x * blockDim.x + threadIdx.x;
    if (e >= EE) return;
    int is64 = g_is64;
    size_t base = (size_t)r * 2 * EE;
    int s = ld_idx(ei, base + e, is64);
    int d = ld_idx(ei, base + EE + e, is64);
    if (g_inb[s] & g_inb[d]) {
        g_app[r][s] = 1;
        g_app[r][d] = 1;
        int j = atomicAdd(&g_cnt[r], 1);
        g_ks[r][j] = s;
        g_kd[r][j] = d;
    }
}

// rank of each appearing node among sorted appearing node ids.
// appearing nodes are a subset of (sorted) batch_nodes, so a 2048-wide scan
// over batch positions gives the same ranks as the full-N cumsum.
__global__ void k_scan() {
    int r = blockIdx.x;
    int t = threadIdx.x;            // 1024 threads, 2 elems each
    __shared__ int sh[1024];
    int v0 = g_bn[2 * t];
    int v1 = g_bn[2 * t + 1];
    int a0 = g_app[r][v0];
    int a1 = g_app[r][v1];
    int ps = a0 + a1;
    sh[t] = ps;
    __syncthreads();
    for (int off = 1; off < 1024; off <<= 1) {
        int val = (t >= off) ? sh[t - off] : 0;
        __syncthreads();
        sh[t] += val;
        __syncthreads();
    }
    int excl = sh[t] - ps;          // exclusive pair-prefix
    if (a0) g_newid[r][v0] = excl + a0 - 1;
    if (a1) g_newid[r][v1] = excl + a0 + a1 - 1;
}

// map kept edges to renumbered ids, accumulate in-degree
__global__ void k_map() {
    int r = blockIdx.y;
    int c = g_cnt[r];
    for (int j = blockIdx.x * blockDim.x + threadIdx.x; j < c;
         j += gridDim.x * blockDim.x) {
        int s = g_newid[r][g_ks[r][j]];
        int d = g_newid[r][g_kd[r][j]];
        g_ks[r][j] = s;
        g_kd[r][j] = d;
        atomicAdd(&g_deg[r][d], 1.0f);
    }
}

__global__ void k_dinv() {
    int i = blockIdx.x * blockDim.x + threadIdx.x;
    if (i < RR * BB) ((float*)g_dinv)[i] = rsqrtf(((float*)g_deg)[i]);
}

// ---------------- GEMM1: xw1 = gather(features) @ W1 ; h = dinv^2*xw1 + b1 ----------------
// BM=128 BN=64 BK=16, 256 threads, 8x4 per thread
__global__ void __launch_bounds__(256) k_gemm1(
    const float* __restrict__ feat,
    const float* __restrict__ W1, const float* __restrict__ b1) {
    const int z = blockIdx.z, bm = blockIdx.x, bnn = blockIdx.y;
    __shared__ float As[16][132];
    __shared__ float Bs[16][64];
    int tid = threadIdx.x;
    int tx = tid & 15, ty = tid >> 4;
    int rowA0 = tid >> 2, kq = tid & 3, rowA1 = rowA0 + 64;
    int n0 = g_bn[bm * 128 + rowA0];
    int n1 = g_bn[bm * 128 + rowA1];
    const float* a0 = feat + ((size_t)z * NN + n0) * INP + kq * 4;
    const float* a1 = feat + ((size_t)z * NN + n1) * INP + kq * 4;
    int krow = tid >> 4, colq = tid & 15;
    const float* bp = W1 + (size_t)krow * HID + bnn * 64 + colq * 4;

    float acc[8][4];
#pragma unroll
    for (int i = 0; i < 8; i++)
#pragma unroll
        for (int j = 0; j < 4; j++) acc[i][j] = 0.f;

    for (int kt = 0; kt < INP; kt += 16) {
        float4 va0 = *(const float4*)(a0 + kt);
        float4 va1 = *(const float4*)(a1 + kt);
        float4 vb  = *(const float4*)(bp + (size_t)kt * HID);
        __syncthreads();
        As[kq * 4 + 0][rowA0] = va0.x; As[kq * 4 + 1][rowA0] = va0.y;
        As[kq * 4 + 2][rowA0] = va0.z; As[kq * 4 + 3][rowA0] = va0.w;
        As[kq * 4 + 0][rowA1] = va1.x; As[kq * 4 + 1][rowA1] = va1.y;
        As[kq * 4 + 2][rowA1] = va1.z; As[kq * 4 + 3][rowA1] = va1.w;
        *(float4*)&Bs[krow][colq * 4] = vb;
        __syncthreads();
#pragma unroll
        for (int kk = 0; kk < 16; kk++) {
            float4 A0 = *(const float4*)&As[kk][ty * 8];
            float4 A1 = *(const float4*)&As[kk][ty * 8 + 4];
            float4 Bv = *(const float4*)&Bs[kk][tx * 4];
            float a[8] = {A0.x, A0.y, A0.z, A0.w, A1.x, A1.y, A1.z, A1.w};
            float b[4] = {Bv.x, Bv.y, Bv.z, Bv.w};
#pragma unroll
            for (int ii = 0; ii < 8; ii++)
#pragma unroll
                for (int jj = 0; jj < 4; jj++) acc[ii][jj] += a[ii] * b[jj];
        }
    }
    int i0 = bm * 128 + ty * 8;
    int c0 = bnn * 64 + tx * 4;
    float4 bv = *(const float4*)(b1 + c0);
    float barr[4] = {bv.x, bv.y, bv.z, bv.w};
#pragma unroll
    for (int ii = 0; ii < 8; ii++) {
        int i = i0 + ii;
        float di = g_dinv[z][i];
        float sc = di * di;
        size_t base = ((size_t)(z * BB + i)) * HID + c0;
#pragma unroll
        for (int jj = 0; jj < 4; jj++) {
            float v = acc[ii][jj];
            g_xw1[base + jj] = v;
            g_h[base + jj] = sc * v + barr[jj];   // self-loop + bias
        }
    }
}

// ---------------- edge scatter into h (conv1 aggregation) ----------------
__global__ void k_scatter1() {
    int r = blockIdx.y;
    int c = g_cnt[r];
    for (int e = blockIdx.x; e < c; e += gridDim.x) {
        int s = g_ks[r][e], d = g_kd[r][e];
        float coeff = g_dinv[r][s] * g_dinv[r][d];
        const float* src = g_xw1 + ((size_t)(r * BB + s)) * HID;
        float* dst = g_h + ((size_t)(r * BB + d)) * HID;
        for (int k = threadIdx.x; k < HID; k += blockDim.x)
            atomicAdd(dst + k, coeff * src[k]);
    }
}

// ---------------- batchnorm ----------------
__global__ void k_bnstats() {
    int r = blockIdx.y;
    int col = threadIdx.x;                 // 512
    int row0 = blockIdx.x * 64;            // 32 blocks
    float s = 0.f, q = 0.f;
    for (int i = 0; i < 64; i++) {
        float v = g_h[((size_t)(r * BB + row0 + i)) * HID + col];
        s += v; q += v * v;
    }
    atomicAdd(&g_bnsum[r][col], s);
    atomicAdd(&g_bnsq[r][col], q);
}

__global__ void k_bnfinal(const float* __restrict__ gamma,
                          const float* __restrict__ beta) {
    int i = blockIdx.x * blockDim.x + threadIdx.x;
    if (i >= RR * HID) return;
    int r = i / HID, c = i % HID;
    float m = g_bnsum[r][c] * (1.0f / BB);
    float v = g_bnsq[r][c] * (1.0f / BB) - m * m;   // biased var
    float istd = rsqrtf(v + 1e-5f);
    float a = gamma[c] * istd;
    g_bna[r][c] = a;
    g_bnb[r][c] = beta[c] - m * a;
}

// ---------------- GEMM2: xw2 = BN(h) @ W2 ; out_init = dinv^2*xw2 + b2 ----------------
__global__ void __launch_bounds__(256) k_gemm2(
    const float* __restrict__ W2, const float* __restrict__ b2,
    float* __restrict__ out) {
    const int z = blockIdx.z, bm = blockIdx.x, bnn = blockIdx.y;
    __shared__ float As[16][132];
    __shared__ float Bs[16][64];
    int tid = threadIdx.x;
    int tx = tid & 15, ty = tid >> 4;
    int rowA0 = tid >> 2, kq = tid & 3, rowA1 = rowA0 + 64;
    const float* a0 = g_h + ((size_t)(z * BB + bm * 128 + rowA0)) * HID + kq * 4;
    const float* a1 = g_h + ((size_t)(z * BB + bm * 128 + rowA1)) * HID + kq * 4;
    const float* pa = &g_bna[z][0] + kq * 4;
    const float* pb = &g_bnb[z][0] + kq * 4;
    int krow = tid >> 4, colq = tid & 15;
    const float* bp = W2 + (size_t)krow * OUTD + bnn * 64 + colq * 4;

    float acc[8][4];
#pragma unroll
    for (int i = 0; i < 8; i++)
#pragma unroll
        for (int j = 0; j < 4; j++) acc[i][j] = 0.f;

    for (int kt = 0; kt < HID; kt += 16) {
        float4 va0 = *(const float4*)(a0 + kt);
        float4 va1 = *(const float4*)(a1 + kt);
        float4 sa  = *(const float4*)(pa + kt);
        float4 sb  = *(const float4*)(pb + kt);
        float4 vb  = *(const float4*)(bp + (size_t)kt * OUTD);
        // fold batchnorm affine into the A operand
        va0.x = va0.x * sa.x + sb.x; va0.y = va0.y * sa.y + sb.y;
        va0.z = va0.z * sa.z + sb.z; va0.w = va0.w * sa.w + sb.w;
        va1.x = va1.x * sa.x + sb.x; va1.y = va1.y * sa.y + sb.y;
        va1.z = va1.z * sa.z + sb.z; va1.w = va1.w * sa.w + sb.w;
        __syncthreads();
        As[kq * 4 + 0][rowA0] = va0.x; As[kq * 4 + 1][rowA0] = va0.y;
        As[kq * 4 + 2][rowA0] = va0.z; As[kq * 4 + 3][rowA0] = va0.w;
        As[kq * 4 + 0][rowA1] = va1.x; As[kq * 4 + 1][rowA1] = va1.y;
        As[kq * 4 + 2][rowA1] = va1.z; As[kq * 4 + 3][rowA1] = va1.w;
        *(float4*)&Bs[krow][colq * 4] = vb;
        __syncthreads();
#pragma unroll
        for (int kk = 0; kk < 16; kk++) {
            float4 A0 = *(const float4*)&As[kk][ty * 8];
            float4 A1 = *(const float4*)&As[kk][ty * 8 + 4];
            float4 Bv = *(const float4*)&Bs[kk][tx * 4];
            float a[8] = {A0.x, A0.y, A0.z, A0.w, A1.x, A1.y, A1.z, A1.w};
            float b[4] = {Bv.x, Bv.y, Bv.z, Bv.w};
#pragma unroll
            for (int ii = 0; ii < 8; ii++)
#pragma unroll
                for (int jj = 0; jj < 4; jj++) acc[ii][jj] += a[ii] * b[jj];
        }
    }
    int i0 = bm * 128 + ty * 8;
    int c0 = bnn * 64 + tx * 4;
    float4 bv = *(const float4*)(b2 + c0);
    float barr[4] = {bv.x, bv.y, bv.z, bv.w};
#pragma unroll
    for (int ii = 0; ii < 8; ii++) {
        int i = i0 + ii;
        float di = g_dinv[z][i];
        float sc = di * di;
        size_t xb = ((size_t)(z * BB + i)) * OUTD + c0;
        float* ob = out + (size_t)z * BB * OUTD + (size_t)i * OUTD + c0;
#pragma unroll
        for (int jj = 0; jj < 4; jj++) {
            float v = acc[ii][jj];
            g_xw2[xb + jj] = v;
            ob[jj] = sc * v + barr[jj];    // self-loop + bias -> output
        }
    }
}

// ---------------- edge scatter into out (conv2 aggregation) ----------------
__global__ void k_scatter2(float* __restrict__ out) {
    int r = blockIdx.y;
    int c = g_cnt[r];
    for (int e = blockIdx.x; e < c; e += gridDim.x) {
        int s = g_ks[r][e], d = g_kd[r][e];
        float coeff = g_dinv[r][s] * g_dinv[r][d];
        const float* src = g_xw2 + ((size_t)(r * BB + s)) * OUTD;
        float* dst = out + (size_t)r * BB * OUTD + (size_t)d * OUTD;
        for (int k = threadIdx.x; k < OUTD; k += blockDim.x)
            atomicAdd(dst + k, coeff * src[k]);
    }
}

// ---------------- launch ----------------
extern "C" void kernel_launch(void* const* d_in, const int* in_sizes, int n_in,
                              void* d_out, int out_size) {
    const float* feat   = (const float*)d_in[0];
    const float* W1     = (const float*)d_in[1];
    const float* b1     = (const float*)d_in[2];
    const float* W2     = (const float*)d_in[3];
    const float* b2     = (const float*)d_in[4];
    const float* gamma  = (const float*)d_in[5];
    const float* beta   = (const float*)d_in[6];
    const void*  ei     = d_in[7];
    const void*  bnodes = d_in[8];
    float* out = (float*)d_out;

    k_detect<<<1, 1>>>(bnodes);
    k_cvt<<<8, 256>>>(bnodes);
    k_init<<<147, 256>>>();
    k_setb<<<8, 256>>>();
    k_mask<<<dim3((EE + 255) / 256, RR), 256>>>(ei);
    k_scan<<<RR, 1024>>>();
    k_map<<<dim3(64, RR), 256>>>();
    k_dinv<<<(RR * BB + 255) / 256, 256>>>();
    k_gemm1<<<dim3(16, 8, RR), 256>>>(feat, W1, b1);
    k_scatter1<<<dim3(1024, RR), 128>>>();
    k_bnstats<<<dim3(32, RR), 512>>>();
    k_bnfinal<<<(RR * HID + 255) / 256, 256>>>(gamma, beta);
    k_gemm2<<<dim3(16, 4, RR), 256>>>(W2, b2, out);
    k_scatter2<<<dim3(1024, RR), 64>>>(out);
}

// round 12
// speedup vs baseline: 1.0823x; 1.0823x over previous
#include <cuda_runtime.h>
#include <cuda_bf16.h>
#include <stdint.h>

#define RR 3
#define NN 50000
#define EE 1000000
#define BB 2048
#define INP 256
#define HID 512
#define OUTD 256

#define SLD 40   // smem K-stride (elements): 20r+c hits all 32 banks distinctly

// ---------------- static scratch (no allocations allowed) ----------------
__device__ int g_bn[BB];
__device__ unsigned char g_inb[NN];
__device__ unsigned char g_app[RR][NN];
__device__ int g_newid[RR][NN];
__device__ int g_cnt[RR];
__device__ int g_ks[RR][EE];
__device__ int g_kd[RR][EE];
__device__ __align__(16) float g_deg[RR][BB];
__device__ __align__(16) float g_xw1[(size_t)RR * BB * HID];
__device__ __align__(16) float g_h[(size_t)RR * BB * HID];
__device__ __align__(16) float g_xw2[(size_t)RR * BB * OUTD];
__device__ __align__(16) float g_bnsum[RR][HID];
__device__ __align__(16) float g_bnsq[RR][HID];
__device__ __align__(16) float g_bna[RR][HID];
__device__ __align__(16) float g_bnb[RR][HID];

// ---------------- helpers ----------------
__device__ __forceinline__ int detect64(const void* bn) {
    long long v = ((const long long*)bn)[0];   // sorted distinct ids: int32 view gives >= 2^32
    return (v >= 0 && v < NN) ? 1 : 0;
}

__device__ __forceinline__ void mma16816(float* c, const uint32_t* a, const uint32_t* b) {
    asm volatile(
        "mma.sync.aligned.m16n8k16.row.col.f32.bf16.bf16.f32 "
        "{%0,%1,%2,%3}, {%4,%5,%6,%7}, {%8,%9}, {%0,%1,%2,%3};"
        : "+f"(c[0]), "+f"(c[1]), "+f"(c[2]), "+f"(c[3])
        : "r"(a[0]), "r"(a[1]), "r"(a[2]), "r"(a[3]), "r"(b[0]), "r"(b[1]));
}

// split fp32x4 -> bf16 hi (truncate) + bf16 lo (rn of residual); 8B-aligned stores
__device__ __forceinline__ void split_store4(__nv_bfloat16* ph, __nv_bfloat16* pl, float4 v) {
    uint32_t b0 = __float_as_uint(v.x), b1 = __float_as_uint(v.y);
    uint32_t b2 = __float_as_uint(v.z), b3 = __float_as_uint(v.w);
    uint2 H;
    H.x = (b0 >> 16) | (b1 & 0xFFFF0000u);
    H.y = (b2 >> 16) | (b3 & 0xFFFF0000u);
    float l0 = v.x - __uint_as_float(b0 & 0xFFFF0000u);
    float l1 = v.y - __uint_as_float(b1 & 0xFFFF0000u);
    float l2 = v.z - __uint_as_float(b2 & 0xFFFF0000u);
    float l3 = v.w - __uint_as_float(b3 & 0xFFFF0000u);
    uint2 L;
    asm("cvt.rn.bf16x2.f32 %0, %1, %2;" : "=r"(L.x) : "f"(l1), "f"(l0));
    asm("cvt.rn.bf16x2.f32 %0, %1, %2;" : "=r"(L.y) : "f"(l3), "f"(l2));
    *(uint2*)ph = H;
    *(uint2*)pl = L;
}
__device__ __forceinline__ void split_store1(__nv_bfloat16* ph, __nv_bfloat16* pl, float v) {
    uint32_t b = __float_as_uint(v);
    *(uint16_t*)ph = (uint16_t)(b >> 16);
    float lo = v - __uint_as_float(b & 0xFFFF0000u);
    uint32_t lb;
    asm("cvt.rn.bf16x2.f32 %0, %1, %2;" : "=r"(lb) : "f"(0.f), "f"(lo));
    *(uint16_t*)pl = (uint16_t)lb;
}

// ---------------- prep: reset replay state + convert batch ids + membership ----------------
__global__ void k_prep(const void* __restrict__ bn) {
    int i = blockIdx.x * blockDim.x + threadIdx.x;   // 16384 threads
    for (int j = i; j < (RR * NN) / 4; j += 16384) ((int*)g_app)[j] = 0;
    if (i < RR) g_cnt[i] = 0;
    if (i < RR * HID) { ((float*)g_bnsum)[i] = 0.f; ((float*)g_bnsq)[i] = 0.f; }
    if (i < RR * BB) ((float*)g_deg)[i] = 1.0f;      // self loop
    if (i < BB) {
        int is64 = detect64(bn);
        int v = is64 ? (int)((const long long*)bn)[i] : ((const int*)bn)[i];
        g_bn[i] = v;
        g_inb[v] = 1;
    }
}

// ---------------- mask + compact kept edges (4 edges/thread) ----------------
__global__ void k_mask(const void* __restrict__ ei, const void* __restrict__ bn) {
    int r = blockIdx.y;
    int e0 = (blockIdx.x * blockDim.x + threadIdx.x) * 4;
    if (e0 >= EE) return;
    int is64 = detect64(bn);
    int s[4], d[4];
    if (is64) {
        const long long* b = (const long long*)ei + (size_t)r * 2 * EE;
        longlong2 s01 = *(const longlong2*)(b + e0);
        longlong2 s23 = *(const longlong2*)(b + e0 + 2);
        longlong2 d01 = *(const longlong2*)(b + EE + e0);
        longlong2 d23 = *(const longlong2*)(b + EE + e0 + 2);
        s[0] = (int)s01.x; s[1] = (int)s01.y; s[2] = (int)s23.x; s[3] = (int)s23.y;
        d[0] = (int)d01.x; d[1] = (int)d01.y; d[2] = (int)d23.x; d[3] = (int)d23.y;
    } else {
        const int* b = (const int*)ei + (size_t)r * 2 * EE;
        int4 sv = *(const int4*)(b + e0);
        int4 dv = *(const int4*)(b + EE + e0);
        s[0] = sv.x; s[1] = sv.y; s[2] = sv.z; s[3] = sv.w;
        d[0] = dv.x; d[1] = dv.y; d[2] = dv.z; d[3] = dv.w;
    }
#pragma unroll
    for (int q = 0; q < 4; q++) {
        if (g_inb[s[q]] & g_inb[d[q]]) {
            g_app[r][s[q]] = 1;
            g_app[r][d[q]] = 1;
            int j = atomicAdd(&g_cnt[r], 1);
            g_ks[r][j] = s[q];
            g_kd[r][j] = d[q];
        }
    }
}

// rank of appearing nodes among sorted appearing ids (subset of sorted batch ids)
__global__ void k_scan() {
    int r = blockIdx.x;
    int t = threadIdx.x;            // 1024 threads, 2 elems each
    __shared__ int sh[1024];
    int v0 = g_bn[2 * t], v1 = g_bn[2 * t + 1];
    int a0 = g_app[r][v0], a1 = g_app[r][v1];
    int ps = a0 + a1;
    sh[t] = ps;
    __syncthreads();
    for (int off = 1; off < 1024; off <<= 1) {
        int val = (t >= off) ? sh[t - off] : 0;
        __syncthreads();
        sh[t] += val;
        __syncthreads();
    }
    int excl = sh[t] - ps;
    if (a0) g_newid[r][v0] = excl + a0 - 1;
    if (a1) g_newid[r][v1] = excl + a0 + a1 - 1;
}

__global__ void k_map() {
    int r = blockIdx.y;
    int c = g_cnt[r];
    for (int j = blockIdx.x * blockDim.x + threadIdx.x; j < c; j += gridDim.x * blockDim.x) {
        int s = g_newid[r][g_ks[r][j]];
        int d = g_newid[r][g_kd[r][j]];
        g_ks[r][j] = s;
        g_kd[r][j] = d;
        atomicAdd(&g_deg[r][d], 1.0f);
    }
}

// ---------------- GEMM1 (mma.sync split-bf16): xw1 = gather(feat)@W1 ; h = dinv^2*xw1 + b1 ----
// block tile 128x128, K-chunk 32, 8 warps as 2(M)x4(N): warp tile 64x32 = 4x4 m16n8k16 atoms
__global__ void __launch_bounds__(256) k_gemm1(
    const float* __restrict__ feat, const float* __restrict__ W1, const float* __restrict__ b1) {
    __shared__ __align__(16) __nv_bfloat16 Ah[128][SLD], Al[128][SLD];
    __shared__ __align__(16) __nv_bfloat16 Bh[128][SLD], Bl[128][SLD];
    const int z = blockIdx.z, bm = blockIdx.x, bnn = blockIdx.y;
    int tid = threadIdx.x, lane = tid & 31, wid = tid >> 5;
    int warpM = wid >> 2, warpN = wid & 3;
    int gID = lane >> 2, qID = lane & 3;

    float acc[4][4][4];
#pragma unroll
    for (int a = 0; a < 4; a++)
#pragma unroll
        for (int b = 0; b < 4; b++)
#pragma unroll
            for (int k = 0; k < 4; k++) acc[a][b][k] = 0.f;

    int ar = tid >> 1, ah = tid & 1;
    const float* arow = feat + ((size_t)z * NN + g_bn[bm * 128 + ar]) * INP + ah * 16;
    int nb = (lane) * 4, kl = wid;   // B: 32 lanes * 4 cols, 8 warps -> k rows
    const float* wb = W1 + bnn * 128 + nb;

    for (int c = 0; c < INP / 32; c++) {
        int k0 = c * 32;
        if (c) __syncthreads();
#pragma unroll
        for (int i = 0; i < 4; i++) {
            float4 v = *(const float4*)(arow + k0 + i * 4);
            int cc = ah * 16 + i * 4;
            split_store4(&Ah[ar][cc], &Al[ar][cc], v);
        }
#pragma unroll
        for (int i = 0; i < 4; i++) {
            int k = kl + i * 8;
            float4 v = *(const float4*)(wb + (size_t)(k0 + k) * HID);
            split_store1(&Bh[nb + 0][k], &Bl[nb + 0][k], v.x);
            split_store1(&Bh[nb + 1][k], &Bl[nb + 1][k], v.y);
            split_store1(&Bh[nb + 2][k], &Bl[nb + 2][k], v.z);
            split_store1(&Bh[nb + 3][k], &Bl[nb + 3][k], v.w);
        }
        __syncthreads();
#pragma unroll
        for (int ks = 0; ks < 2; ks++) {
            int kc = ks * 16 + qID * 2;
            uint32_t fah[4][4], fal[4][4], fbh[4][2], fbl[4][2];
#pragma unroll
            for (int am = 0; am < 4; am++) {
                int r0 = warpM * 64 + am * 16 + gID;
                fah[am][0] = *(const uint32_t*)&Ah[r0][kc];
                fah[am][1] = *(const uint32_t*)&Ah[r0 + 8][kc];
                fah[am][2] = *(const uint32_t*)&Ah[r0][kc + 8];
                fah[am][3] = *(const uint32_t*)&Ah[r0 + 8][kc + 8];
                fal[am][0] = *(const uint32_t*)&Al[r0][kc];
                fal[am][1] = *(const uint32_t*)&Al[r0 + 8][kc];
                fal[am][2] = *(const uint32_t*)&Al[r0][kc + 8];
                fal[am][3] = *(const uint32_t*)&Al[r0 + 8][kc + 8];
            }
#pragma unroll
            for (int bn = 0; bn < 4; bn++) {
                int n0 = warpN * 32 + bn * 8 + gID;
                fbh[bn][0] = *(const uint32_t*)&Bh[n0][kc];
                fbh[bn][1] = *(const uint32_t*)&Bh[n0][kc + 8];
                fbl[bn][0] = *(const uint32_t*)&Bl[n0][kc];
                fbl[bn][1] = *(const uint32_t*)&Bl[n0][kc + 8];
            }
#pragma unroll
            for (int am = 0; am < 4; am++)
#pragma unroll
                for (int bn = 0; bn < 4; bn++) {
                    mma16816(acc[am][bn], fah[am], fbh[bn]);
                    mma16816(acc[am][bn], fal[am], fbh[bn]);
                    mma16816(acc[am][bn], fah[am], fbl[bn]);
                }
        }
    }
    // epilogue
#pragma unroll
    for (int am = 0; am < 4; am++) {
        int r0 = bm * 128 + warpM * 64 + am * 16 + gID;
        float d0 = rsqrtf(g_deg[z][r0]);
        float d1 = rsqrtf(g_deg[z][r0 + 8]);
        float s0 = d0 * d0, s1 = d1 * d1;
#pragma unroll
        for (int bn = 0; bn < 4; bn++) {
            int cg = bnn * 128 + warpN * 32 + bn * 8 + qID * 2;
            float2 bb = *(const float2*)&b1[cg];
            size_t o0 = ((size_t)z * BB + r0) * HID + cg;
            size_t o1 = ((size_t)z * BB + r0 + 8) * HID + cg;
            float* p = acc[am][bn];
            *(float2*)&g_xw1[o0] = make_float2(p[0], p[1]);
            *(float2*)&g_h[o0] = make_float2(s0 * p[0] + bb.x, s0 * p[1] + bb.y);
            *(float2*)&g_xw1[o1] = make_float2(p[2], p[3]);
            *(float2*)&g_h[o1] = make_float2(s1 * p[2] + bb.x, s1 * p[3] + bb.y);
        }
    }
}

// ---------------- edge scatter into h ----------------
__global__ void k_scatter1() {
    int r = blockIdx.y;
    int c = g_cnt[r];
    for (int e = blockIdx.x; e < c; e += 512) {
        int s = g_ks[r][e], d = g_kd[r][e];
        float coeff = rsqrtf(g_deg[r][s]) * rsqrtf(g_deg[r][d]);
        const float* src = g_xw1 + ((size_t)(r * BB + s)) * HID;
        float* dst = g_h + ((size_t)(r * BB + d)) * HID;
        for (int k = threadIdx.x; k < HID; k += blockDim.x)
            atomicAdd(dst + k, coeff * src[k]);
    }
}

// ---------------- batchnorm ----------------
__global__ void k_bnstats() {
    int r = blockIdx.y;
    int col = threadIdx.x;                 // 512
    int row0 = blockIdx.x * 64;            // 32 blocks
    float s = 0.f, q = 0.f;
    for (int i = 0; i < 64; i++) {
        float v = g_h[((size_t)(r * BB + row0 + i)) * HID + col];
        s += v; q += v * v;
    }
    atomicAdd(&g_bnsum[r][col], s);
    atomicAdd(&g_bnsq[r][col], q);
}

__global__ void k_bnfinal(const float* __restrict__ gamma, const float* __restrict__ beta) {
    int i = blockIdx.x * blockDim.x + threadIdx.x;
    if (i >= RR * HID) return;
    int r = i / HID, c = i % HID;
    float m = g_bnsum[r][c] * (1.0f / BB);
    float v = g_bnsq[r][c] * (1.0f / BB) - m * m;
    float istd = rsqrtf(v + 1e-5f);
    float a = gamma[c] * istd;
    g_bna[r][c] = a;
    g_bnb[r][c] = beta[c] - m * a;
}

// ---------------- GEMM2 (mma.sync split-bf16): xw2 = BN(h)@W2 ; out = dinv^2*xw2 + b2 -------
// block tile 128x64, K-chunk 32, 8 warps as 4(M)x2(N): warp tile 32x32 = 2x4 atoms
__global__ void __launch_bounds__(256) k_gemm2(
    const float* __restrict__ W2, const float* __restrict__ b2, float* __restrict__ out) {
    __shared__ __align__(16) __nv_bfloat16 Ah[128][SLD], Al[128][SLD];
    __shared__ __align__(16) __nv_bfloat16 Bh[64][SLD], Bl[64][SLD];
    const int z = blockIdx.z, bm = blockIdx.x, bnn = blockIdx.y;
    int tid = threadIdx.x, lane = tid & 31, wid = tid >> 5;
    int warpM = wid >> 1, warpN = wid & 1;
    int gID = lane >> 2, qID = lane & 3;

    float acc[2][4][4];
#pragma unroll
    for (int a = 0; a < 2; a++)
#pragma unroll
        for (int b = 0; b < 4; b++)
#pragma unroll
            for (int k = 0; k < 4; k++) acc[a][b][k] = 0.f;

    int ar = tid >> 1, ah = tid & 1;
    const float* arow = g_h + ((size_t)(z * BB + bm * 128 + ar)) * HID + ah * 16;
    const float* pa = &g_bna[z][0] + ah * 16;
    const float* pb = &g_bnb[z][0] + ah * 16;
    int nb = (tid & 15) * 4, kl = tid >> 4;   // 16 lanes * 4 cols, 16 k rows
    const float* wb = W2 + bnn * 64 + nb;

    for (int c = 0; c < HID / 32; c++) {
        int k0 = c * 32;
        if (c) __syncthreads();
#pragma unroll
        for (int i = 0; i < 4; i++) {
            float4 hv = *(const float4*)(arow + k0 + i * 4);
            float4 av = *(const float4*)(pa + k0 + i * 4);
            float4 bv = *(const float4*)(pb + k0 + i * 4);
            float4 v;
            v.x = hv.x * av.x + bv.x; v.y = hv.y * av.y + bv.y;
            v.z = hv.z * av.z + bv.z; v.w = hv.w * av.w + bv.w;
            int cc = ah * 16 + i * 4;
            split_store4(&Ah[ar][cc], &Al[ar][cc], v);
        }
#pragma unroll
        for (int i = 0; i < 2; i++) {
            int k = kl + i * 16;
            float4 v = *(const float4*)(wb + (size_t)(k0 + k) * OUTD);
            split_store1(&Bh[nb + 0][k], &Bl[nb + 0][k], v.x);
            split_store1(&Bh[nb + 1][k], &Bl[nb + 1][k], v.y);
            split_store1(&Bh[nb + 2][k], &Bl[nb + 2][k], v.z);
            split_store1(&Bh[nb + 3][k], &Bl[nb + 3][k], v.w);
        }
        __syncthreads();
#pragma unroll
        for (int ks = 0; ks < 2; ks++) {
            int kc = ks * 16 + qID * 2;
            uint32_t fah[2][4], fal[2][4], fbh[4][2], fbl[4][2];
#pragma unroll
            for (int am = 0; am < 2; am++) {
                int r0 = warpM * 32 + am * 16 + gID;
                fah[am][0] = *(const uint32_t*)&Ah[r0][kc];
                fah[am][1] = *(const uint32_t*)&Ah[r0 + 8][kc];
                fah[am][2] = *(const uint32_t*)&Ah[r0][kc + 8];
                fah[am][3] = *(const uint32_t*)&Ah[r0 + 8][kc + 8];
                fal[am][0] = *(const uint32_t*)&Al[r0][kc];
                fal[am][1] = *(const uint32_t*)&Al[r0 + 8][kc];
                fal[am][2] = *(const uint32_t*)&Al[r0][kc + 8];
                fal[am][3] = *(const uint32_t*)&Al[r0 + 8][kc + 8];
            }
#pragma unroll
            for (int bn = 0; bn < 4; bn++) {
                int n0 = warpN * 32 + bn * 8 + gID;
                fbh[bn][0] = *(const uint32_t*)&Bh[n0][kc];
                fbh[bn][1] = *(const uint32_t*)&Bh[n0][kc + 8];
                fbl[bn][0] = *(const uint32_t*)&Bl[n0][kc];
                fbl[bn][1] = *(const uint32_t*)&Bl[n0][kc + 8];
            }
#pragma unroll
            for (int am = 0; am < 2; am++)
#pragma unroll
                for (int bn = 0; bn < 4; bn++) {
                    mma16816(acc[am][bn], fah[am], fbh[bn]);
                    mma16816(acc[am][bn], fal[am], fbh[bn]);
                    mma16816(acc[am][bn], fah[am], fbl[bn]);
                }
        }
    }
#pragma unroll
    for (int am = 0; am < 2; am++) {
        int r0 = bm * 128 + warpM * 32 + am * 16 + gID;
        float d0 = rsqrtf(g_deg[z][r0]);
        float d1 = rsqrtf(g_deg[z][r0 + 8]);
        float s0 = d0 * d0, s1 = d1 * d1;
#pragma unroll
        for (int bn = 0; bn < 4; bn++) {
            int cg = bnn * 64 + warpN * 32 + bn * 8 + qID * 2;
            float2 bb = *(const float2*)&b2[cg];
            size_t o0 = ((size_t)z * BB + r0) * OUTD + cg;
            size_t o1 = ((size_t)z * BB + r0 + 8) * OUTD + cg;
            float* p = acc[am][bn];
            *(float2*)&g_xw2[o0] = make_float2(p[0], p[1]);
            *(float2*)&out[o0] = make_float2(s0 * p[0] + bb.x, s0 * p[1] + bb.y);
            *(float2*)&g_xw2[o1] = make_float2(p[2], p[3]);
            *(float2*)&out[o1] = make_float2(s1 * p[2] + bb.x, s1 * p[3] + bb.y);
        }
    }
}

// ---------------- edge scatter into out + replay-state cleanup ----------------
__global__ void k_scatter2(float* __restrict__ out) {
    int r = blockIdx.y;
    if (blockIdx.x == 512) {   // cleanup block: clear membership bits for next replay
        if (r == 0)
            for (int i = threadIdx.x; i < BB; i += blockDim.x) g_inb[g_bn[i]] = 0;
        return;
    }
    int c = g_cnt[r];
    for (int e = blockIdx.x; e < c; e += 512) {
        int s = g_ks[r][e], d = g_kd[r][e];
        float coeff = rsqrtf(g_deg[r][s]) * rsqrtf(g_deg[r][d]);
        const float* src = g_xw2 + ((size_t)(r * BB + s)) * OUTD;
        float* dst = out + (size_t)r * BB * OUTD + (size_t)d * OUTD;
        for (int k = threadIdx.x; k < OUTD; k += blockDim.x)
            atomicAdd(dst + k, coeff * src[k]);
    }
}

// ---------------- launch ----------------
extern "C" void kernel_launch(void* const* d_in, const int* in_sizes, int n_in,
                              void* d_out, int out_size) {
    const float* feat  = (const float*)d_in[0];
    const float* W1    = (const float*)d_in[1];
    const float* b1    = (const float*)d_in[2];
    const float* W2    = (const float*)d_in[3];
    const float* b2    = (const float*)d_in[4];
    const float* gamma = (const float*)d_in[5];
    const float* beta  = (const float*)d_in[6];
    const void*  ei    = d_in[7];
    const void*  bn    = d_in[8];
    float* out = (float*)d_out;

    k_prep<<<64, 256>>>(bn);
    k_mask<<<dim3((EE / 4 + 255) / 256, RR), 256>>>(ei, bn);   // 977 blocks: covers all EE
    k_scan<<<RR, 1024>>>();
    k_map<<<dim3(32, RR), 256>>>();
    k_gemm1<<<dim3(16, HID / 128, RR), 256>>>(feat, W1, b1);
    k_scatter1<<<dim3(512, RR), 128>>>();
    k_bnstats<<<dim3(32, RR), 512>>>();
    k_bnfinal<<<6, 256>>>(gamma, beta);
    k_gemm2<<<dim3(16, OUTD / 64, RR), 256>>>(W2, b2, out);
    k_scatter2<<<dim3(513, RR), 128>>>(out);
}